// round 16
// baseline (speedup 1.0000x reference)
#include <cuda_runtime.h>
#include <cstdint>
#include <cstddef>

#define T_STEPS  100
#define BATCH    256
#define IN_DIM   1024
#define HID      2048
#define OUT_DIM  10
#define DECAY    0.9f
#define THRESH   1.0f
#define BS_P     132                     // Bs row pitch in floats (128 + 4)
#define CHUNK_FL (32 * BS_P)             // 4224 floats per staged chunk
#define POOL_FL  (3 * CHUNK_FL)          // three 32-k chunks of 128 n
#define SMEM_DYN (POOL_FL * 4 + 32 * 32) // 50688 + 1024 nibble scratch

// ---------------- device scratch (static, no allocations) ----------------
__device__ unsigned g_mX[(size_t)T_STEPS * BATCH * 32];  // input bits: [t][b][32 words]
__device__ unsigned g_m1[2][BATCH * 64];                 // layer1 spike bits (A for L2)
__device__ unsigned g_m2[2][BATCH * 64];                 // layer2 spike bits (for OUT)
__device__ float g_v1[BATCH * HID];
__device__ float g_v2[BATCH * HID];
__device__ float g_vout[BATCH * OUT_DIM];
__device__ float g_acc[BATCH * OUT_DIM];

// ---------------- helpers ----------------
__device__ __forceinline__ uint32_t smem_u32(const void* p) {
    uint32_t a;
    asm("{ .reg .u64 t; cvta.to.shared.u64 t, %1; cvt.u32.u64 %0, t; }" : "=r"(a) : "l"(p));
    return a;
}
__device__ __forceinline__ void cp16(uint32_t dst, const void* src) {
    asm volatile("cp.async.cg.shared.global [%0], [%1], 16;" :: "r"(dst), "l"(src) : "memory");
}
#define CP_COMMIT() asm volatile("cp.async.commit_group;" ::: "memory")

// ---------------- build input bitmasks: in[b][i][t] -> g_mX[t][b][i/32] ----------------
__global__ void maskify_kernel(const float* __restrict__ in)
{
    __shared__ float tile[32][33];
    int t0  = blockIdx.x * 32;
    int bi0 = blockIdx.y * 32;           // 32 consecutive (b,i); same b (1024%32==0)
    int tx = threadIdx.x, ty = threadIdx.y;

    #pragma unroll
    for (int r = ty; r < 32; r += 8) {
        int bi = bi0 + r, t = t0 + tx;
        tile[r][tx] = (t < T_STEPS) ? in[(size_t)bi * T_STEPS + t] : 0.0f;
    }
    __syncthreads();
    if (ty == 0) {
        int t = t0 + tx;
        if (t < T_STEPS) {
            unsigned w = 0;
            #pragma unroll
            for (int j = 0; j < 32; j++)
                if (tile[j][tx] != 0.0f) w |= (1u << j);
            int b  = bi0 >> 10;
            int iw = (bi0 & 1023) >> 5;
            g_mX[(size_t)t * (BATCH * 32) + b * 32 + iw] = w;
        }
    }
}

__global__ void zero_state_kernel()
{
    int i = blockIdx.x * 256 + threadIdx.x;
    if (i < BATCH * HID) { g_v1[i] = 0.0f; g_v2[i] = 0.0f; }
    if (i < BATCH * OUT_DIM) { g_vout[i] = 0.0f; g_acc[i] = 0.0f; }
}

// ---------------- per-row sparse accumulate (ascending k, single accumulator) ----------------
__device__ __forceinline__ void accum_mask(unsigned mask, const float* __restrict__ Bsb,
                                           int c0, float* __restrict__ acc)
{
    while (__popc(mask) >= 4) {
        int k0 = __ffs(mask) - 1; mask &= mask - 1;
        int k1 = __ffs(mask) - 1; mask &= mask - 1;
        int k2 = __ffs(mask) - 1; mask &= mask - 1;
        int k3 = __ffs(mask) - 1; mask &= mask - 1;
        float4 x0 = *(const float4*)&Bsb[k0 * BS_P + c0];
        float4 x1 = *(const float4*)&Bsb[k1 * BS_P + c0];
        float4 x2 = *(const float4*)&Bsb[k2 * BS_P + c0];
        float4 x3 = *(const float4*)&Bsb[k3 * BS_P + c0];
        acc[0] += x0.x; acc[1] += x0.y; acc[2] += x0.z; acc[3] += x0.w;
        acc[0] += x1.x; acc[1] += x1.y; acc[2] += x1.z; acc[3] += x1.w;
        acc[0] += x2.x; acc[1] += x2.y; acc[2] += x2.z; acc[3] += x2.w;
        acc[0] += x3.x; acc[1] += x3.y; acc[2] += x3.z; acc[3] += x3.w;
    }
    while (mask) {
        int k = __ffs(mask) - 1; mask &= mask - 1;
        float4 b0 = *(const float4*)&Bsb[k * BS_P + c0];
        acc[0] += b0.x; acc[1] += b0.y; acc[2] += b0.z; acc[3] += b0.w;
    }
}

// ---------------- sparse GEMM tile (32m x 128n, 2 m-rows per warp) + LIF + mask out ----------------
// acc[n] = sum over active k (ascending) of W[k][n]; bitwise identical to the dense
// ascending-k fma chain (fma(0,w,acc)==acc, fma(1,w,acc)==acc+w exactly).
__device__ __forceinline__ void gemm_sparse(
    const unsigned* __restrict__ Am, int ws,      // A bitmask rows, words per row
    const float* __restrict__ B,                  // W [K][2048]
    float* __restrict__ v, unsigned* __restrict__ mOut,
    int K, int bx, int by, float* pool, unsigned char* nib)
{
    int tid  = threadIdx.x;
    int wid  = tid >> 5, lane = tid & 31;
    int m0   = by * 32, n0 = bx * 128;
    int mA   = m0 + wid * 2;              // two rows per warp: mA, mA+1
    int c0   = lane * 4;

    float acc[2][4] = {{0.f,0.f,0.f,0.f},{0.f,0.f,0.f,0.f}};
    const int nch = K / 32;

    // stage mapping: 32 k-rows x 32 float4 cols, 512 threads x 2 cp16
    int kRow = tid >> 4;                 // 0..31
    int f0   = tid & 15;                 // float4 col base (+16e)
    uint32_t sb[3] = { smem_u32(pool), smem_u32(pool + CHUNK_FL),
                       smem_u32(pool + 2 * CHUNK_FL) };

    // prologue: stage chunks 0 and 1
    #pragma unroll
    for (int e = 0; e < 2; e++)
        cp16(sb[0] + (uint32_t)(kRow * BS_P + (f0 + 16 * e) * 4) * 4,
             B + (size_t)kRow * HID + n0 + (f0 + 16 * e) * 4);
    CP_COMMIT();
    if (nch > 1) {
        #pragma unroll
        for (int e = 0; e < 2; e++)
            cp16(sb[1] + (uint32_t)(kRow * BS_P + (f0 + 16 * e) * 4) * 4,
                 B + (size_t)(32 + kRow) * HID + n0 + (f0 + 16 * e) * 4);
        CP_COMMIT();
    }

    int bufIdx = 0;
    for (int ch = 0; ch < nch; ch++) {
        unsigned maskA = Am[(size_t)mA * ws + ch];         // issue early (hide LDG)
        unsigned maskB = Am[(size_t)(mA + 1) * ws + ch];

        if (ch + 1 < nch) asm volatile("cp.async.wait_group 1;" ::: "memory");
        else              asm volatile("cp.async.wait_group 0;" ::: "memory");
        __syncthreads();   // buf[bufIdx] staged AND reads of the buf to be
                           // overwritten (used at ch-1) are complete

        // stage chunk ch+2 into the buffer freed at ch-1
        if (ch + 2 < nch) {
            int nb = bufIdx + 2; if (nb >= 3) nb -= 3;
            int k0 = (ch + 2) * 32;
            uint32_t dn = sb[nb];
            #pragma unroll
            for (int e = 0; e < 2; e++)
                cp16(dn + (uint32_t)(kRow * BS_P + (f0 + 16 * e) * 4) * 4,
                     B + (size_t)(k0 + kRow) * HID + n0 + (f0 + 16 * e) * 4);
            CP_COMMIT();
        }

        const float* Bsb = pool + bufIdx * CHUNK_FL;
        accum_mask(maskA, Bsb, c0, acc[0]);
        accum_mask(maskB, Bsb, c0, acc[1]);

        if (++bufIdx == 3) bufIdx = 0;
    }

    // ---- fused LIF epilogue + spike-bit packing (two rows) ----
    #pragma unroll
    for (int r = 0; r < 2; r++) {
        size_t base = (size_t)(mA + r) * HID + n0 + c0;
        float4 vv = *(const float4*)&v[base];
        float t0 = vv.x * DECAY + acc[r][0];
        float t1 = vv.y * DECAY + acc[r][1];
        float t2 = vv.z * DECAY + acc[r][2];
        float t3 = vv.w * DECAY + acc[r][3];
        bool p0 = t0 >= THRESH, p1 = t1 >= THRESH, p2 = t2 >= THRESH, p3 = t3 >= THRESH;
        float4 vn;
        vn.x = p0 ? 0.0f : t0; vn.y = p1 ? 0.0f : t1;
        vn.z = p2 ? 0.0f : t2; vn.w = p3 ? 0.0f : t3;
        *(float4*)&v[base] = vn;
        unsigned nb = (unsigned)p0 | ((unsigned)p1 << 1) | ((unsigned)p2 << 2) | ((unsigned)p3 << 3);
        nib[(wid * 2 + r) * 32 + lane] = (unsigned char)nb;
    }
    __syncwarp();
    if (lane < 8) {                                 // 2 rows x 4 words of 32 bits
        int r = lane >> 2, widx = lane & 3;
        unsigned w = 0;
        #pragma unroll
        for (int q = 0; q < 8; q++)
            w |= (unsigned)nib[(wid * 2 + r) * 32 + widx * 8 + q] << (4 * q);
        mOut[(size_t)(mA + r) * 64 + (n0 >> 5) + widx] = w;
    }
}

// ---------------- fused step: [0,128)=L2(t), [128,256)=L1(t+1), [256,320)=OUT(t-1) ----------------
__global__ __launch_bounds__(512, 3) void fused_step_kernel(
    const unsigned* __restrict__ mXt,
    const float* __restrict__ W_ih,
    const float* __restrict__ W_hh,
    const float* __restrict__ W_ho,
    const unsigned* __restrict__ m1r, unsigned* __restrict__ m1w,
    const unsigned* __restrict__ m2r, unsigned* __restrict__ m2w,
    int doL1, int doL2, int doOUT)
{
    extern __shared__ char dyn[];
    float* pool = (float*)dyn;
    unsigned char* nib = (unsigned char*)(dyn + POOL_FL * 4);
    int blk = blockIdx.x;
    int tid = threadIdx.x;

    if (blk < 128) {                       // ---- L2(t): m1 @ W_hh -> v2, m2
        if (!doL2) return;
        gemm_sparse(m1r, 64, W_hh, g_v2, m2w, HID, blk & 15, blk >> 4, pool, nib);
    } else if (blk < 256) {                // ---- L1(t+1): mX @ W_ih -> v1, m1
        if (!doL1) return;
        int b2 = blk - 128;
        gemm_sparse(mXt, 32, W_ih, g_v1, m1w, IN_DIM, b2 & 15, b2 >> 4, pool, nib);
    } else {                               // ---- OUT(t-1): mask-driven, order == validated kernel
        if (!doOUT) return;
        int group = tid >> 7;              // 0..3
        int lt    = tid & 127;
        int b     = (blk - 256) * 4 + group;

        float accv[OUT_DIM];
        #pragma unroll
        for (int o = 0; o < OUT_DIM; o++) accv[o] = 0.0f;

        const unsigned* mrow = m2r + (size_t)b * 64;
        #pragma unroll 4
        for (int j = 0; j < HID / 128; j++) {
            int i = lt + j * 128;
            unsigned w = mrow[i >> 5];
            if ((w >> (i & 31)) & 1u) {
                #pragma unroll
                for (int o = 0; o < OUT_DIM; o++)
                    accv[o] += W_ho[(size_t)i * OUT_DIM + o];
            }
        }

        float* red = pool;                 // [4][OUT_DIM][128] = 5120 floats
        #pragma unroll
        for (int o = 0; o < OUT_DIM; o++) red[(group * OUT_DIM + o) * 128 + lt] = accv[o];
        __syncthreads();

        for (int stride = 64; stride > 0; stride >>= 1) {
            if (lt < stride) {
                #pragma unroll
                for (int o = 0; o < OUT_DIM; o++)
                    red[(group * OUT_DIM + o) * 128 + lt] +=
                        red[(group * OUT_DIM + o) * 128 + lt + stride];
            }
            __syncthreads();
        }

        if (lt < OUT_DIM) {
            float cur = red[(group * OUT_DIM + lt) * 128];
            int idx = b * OUT_DIM + lt;
            float vv = g_vout[idx] * DECAY + cur;
            bool sp = (vv >= THRESH);
            g_vout[idx] = sp ? 0.0f : vv;
            if (sp) g_acc[idx] += 1.0f;
        }
    }
}

__global__ void finalize_kernel(float* __restrict__ out)
{
    int i = blockIdx.x * 256 + threadIdx.x;
    if (i < BATCH * OUT_DIM) out[i] = g_acc[i] * (1.0f / T_STEPS);
}

// ---------------- launch ----------------
extern "C" void kernel_launch(void* const* d_in, const int* in_sizes, int n_in,
                              void* d_out, int out_size)
{
    const float* in_bins = (const float*)d_in[0];   // [256,1024,100]
    const float* W_ih    = (const float*)d_in[1];   // [1024,2048]
    const float* W_hh    = (const float*)d_in[2];   // [1,2048,2048]
    const float* W_ho    = (const float*)d_in[3];   // [2048,10]
    float* out = (float*)d_out;

    unsigned *mX, *m1, *m2;
    cudaGetSymbolAddress((void**)&mX, g_mX);
    cudaGetSymbolAddress((void**)&m1, g_m1);
    cudaGetSymbolAddress((void**)&m2, g_m2);

    cudaFuncSetAttribute(fused_step_kernel,
                         cudaFuncAttributeMaxDynamicSharedMemorySize, SMEM_DYN);

    // 1) build input bitmasks
    {
        dim3 grid((T_STEPS + 31) / 32, (BATCH * IN_DIM) / 32);
        maskify_kernel<<<grid, dim3(32, 8)>>>(in_bins);
    }
    // 2) zero persistent state
    zero_state_kernel<<<(BATCH * HID + 255) / 256, 256>>>();

    // 3) software-pipelined time loop: call i runs L1(t=i), L2(t=i-1), OUT(t=i-2)
    for (int i = 0; i <= T_STEPS + 1; i++) {
        int ti = (i < T_STEPS) ? i : (T_STEPS - 1);
        const unsigned* mXt = mX + (size_t)ti * (BATCH * 32);
        unsigned* m1w = m1 + (size_t)(i & 1) * (BATCH * 64);
        const unsigned* m1r = m1 + (size_t)((i - 1) & 1) * (BATCH * 64);
        unsigned* m2w = m2 + (size_t)((i - 1) & 1) * (BATCH * 64);
        const unsigned* m2r = m2 + (size_t)((i - 2) & 1) * (BATCH * 64);
        int doL1  = (i < T_STEPS);
        int doL2  = (i >= 1) && (i <= T_STEPS);
        int doOUT = (i >= 2);
        fused_step_kernel<<<320, 512, SMEM_DYN>>>(mXt, W_ih, W_hh, W_ho,
                                                  m1r, m1w, m2r, m2w,
                                                  doL1, doL2, doOUT);
    }

    // 4) finalize
    finalize_kernel<<<(BATCH * OUT_DIM + 255) / 256, 256>>>(out);
}

// round 17
// speedup vs baseline: 1.2056x; 1.2056x over previous
#include <cuda_runtime.h>
#include <cstdint>
#include <cstddef>

#define T_STEPS  100
#define BATCH    256
#define IN_DIM   1024
#define HID      2048
#define OUT_DIM  10
#define DECAY    0.9f
#define THRESH   1.0f
#define BS_P     132                     // Bs row pitch in floats (128 + 4)
#define CHUNK_FL (32 * BS_P)             // 4224 floats per staged chunk
#define POOL_FL  (3 * CHUNK_FL)          // three 32-k chunks of 128 n
#define SMEM_DYN (POOL_FL * 4 + 32 * 32) // 50688 + 1024 nibble scratch

// ---------------- device scratch (static, no allocations) ----------------
__device__ unsigned g_mX[(size_t)T_STEPS * BATCH * 32];  // input bits: [t][b][32 words]
__device__ unsigned g_m1[2][BATCH * 64];                 // layer1 spike bits (A for L2)
__device__ unsigned g_m2[2][BATCH * 64];                 // layer2 spike bits (for OUT)
__device__ float g_v1[BATCH * HID];
__device__ float g_v2[BATCH * HID];
__device__ float g_vout[BATCH * OUT_DIM];
__device__ float g_acc[BATCH * OUT_DIM];

// ---------------- helpers ----------------
__device__ __forceinline__ uint32_t smem_u32(const void* p) {
    uint32_t a;
    asm("{ .reg .u64 t; cvta.to.shared.u64 t, %1; cvt.u32.u64 %0, t; }" : "=r"(a) : "l"(p));
    return a;
}
__device__ __forceinline__ void cp16(uint32_t dst, const void* src) {
    asm volatile("cp.async.cg.shared.global [%0], [%1], 16;" :: "r"(dst), "l"(src) : "memory");
}
#define CP_COMMIT() asm volatile("cp.async.commit_group;" ::: "memory")

// ---------------- build input bitmasks: in[b][i][t] -> g_mX[t][b][i/32] ----------------
__global__ void maskify_kernel(const float* __restrict__ in)
{
    __shared__ float tile[32][33];
    int t0  = blockIdx.x * 32;
    int bi0 = blockIdx.y * 32;           // 32 consecutive (b,i); same b (1024%32==0)
    int tx = threadIdx.x, ty = threadIdx.y;

    #pragma unroll
    for (int r = ty; r < 32; r += 8) {
        int bi = bi0 + r, t = t0 + tx;
        tile[r][tx] = (t < T_STEPS) ? in[(size_t)bi * T_STEPS + t] : 0.0f;
    }
    __syncthreads();
    if (ty == 0) {
        int t = t0 + tx;
        if (t < T_STEPS) {
            unsigned w = 0;
            #pragma unroll
            for (int j = 0; j < 32; j++)
                if (tile[j][tx] != 0.0f) w |= (1u << j);
            int b  = bi0 >> 10;
            int iw = (bi0 & 1023) >> 5;
            g_mX[(size_t)t * (BATCH * 32) + b * 32 + iw] = w;
        }
    }
}

__global__ void zero_state_kernel()
{
    int i = blockIdx.x * 256 + threadIdx.x;
    if (i < BATCH * HID) { g_v1[i] = 0.0f; g_v2[i] = 0.0f; }
    if (i < BATCH * OUT_DIM) { g_vout[i] = 0.0f; g_acc[i] = 0.0f; }
}

// ---------------- per-row sparse accumulate (ascending k, single accumulator) ----------------
__device__ __forceinline__ void accum_mask(unsigned mask, const float* __restrict__ Bsb,
                                           int c0, float* __restrict__ acc)
{
    while (__popc(mask) >= 4) {
        int k0 = __ffs(mask) - 1; mask &= mask - 1;
        int k1 = __ffs(mask) - 1; mask &= mask - 1;
        int k2 = __ffs(mask) - 1; mask &= mask - 1;
        int k3 = __ffs(mask) - 1; mask &= mask - 1;
        float4 x0 = *(const float4*)&Bsb[k0 * BS_P + c0];
        float4 x1 = *(const float4*)&Bsb[k1 * BS_P + c0];
        float4 x2 = *(const float4*)&Bsb[k2 * BS_P + c0];
        float4 x3 = *(const float4*)&Bsb[k3 * BS_P + c0];
        acc[0] += x0.x; acc[1] += x0.y; acc[2] += x0.z; acc[3] += x0.w;
        acc[0] += x1.x; acc[1] += x1.y; acc[2] += x1.z; acc[3] += x1.w;
        acc[0] += x2.x; acc[1] += x2.y; acc[2] += x2.z; acc[3] += x2.w;
        acc[0] += x3.x; acc[1] += x3.y; acc[2] += x3.z; acc[3] += x3.w;
    }
    while (mask) {
        int k = __ffs(mask) - 1; mask &= mask - 1;
        float4 b0 = *(const float4*)&Bsb[k * BS_P + c0];
        acc[0] += b0.x; acc[1] += b0.y; acc[2] += b0.z; acc[3] += b0.w;
    }
}

// ---------------- sparse GEMM tile (RPW m-rows per warp x 128n) + LIF + mask out ----------------
// acc[n] = sum over active k (ascending) of W[k][n]; bitwise identical to the dense
// ascending-k fma chain (fma(0,w,acc)==acc, fma(1,w,acc)==acc+w exactly).
template <int RPW>
__device__ __forceinline__ void gemm_sparse(
    const unsigned* __restrict__ Am, int ws,      // A bitmask rows, words per row
    const float* __restrict__ B,                  // W [K][2048]
    float* __restrict__ v, unsigned* __restrict__ mOut,
    int K, int bx, int by, float* pool, unsigned char* nib)
{
    int tid  = threadIdx.x;
    int wid  = tid >> 5, lane = tid & 31;
    int m0   = by * (16 * RPW), n0 = bx * 128;
    int mA   = m0 + wid * RPW;
    int c0   = lane * 4;

    float acc[RPW][4];
    #pragma unroll
    for (int r = 0; r < RPW; r++)
        #pragma unroll
        for (int j = 0; j < 4; j++) acc[r][j] = 0.0f;

    const int nch = K / 32;

    // stage mapping: 32 k-rows x 32 float4 cols, 512 threads x 2 cp16
    int kRow = tid >> 4;                 // 0..31
    int f0   = tid & 15;                 // float4 col base (+16e)
    uint32_t sb[3] = { smem_u32(pool), smem_u32(pool + CHUNK_FL),
                       smem_u32(pool + 2 * CHUNK_FL) };

    // prologue: stage chunks 0 and 1
    #pragma unroll
    for (int e = 0; e < 2; e++)
        cp16(sb[0] + (uint32_t)(kRow * BS_P + (f0 + 16 * e) * 4) * 4,
             B + (size_t)kRow * HID + n0 + (f0 + 16 * e) * 4);
    CP_COMMIT();
    if (nch > 1) {
        #pragma unroll
        for (int e = 0; e < 2; e++)
            cp16(sb[1] + (uint32_t)(kRow * BS_P + (f0 + 16 * e) * 4) * 4,
                 B + (size_t)(32 + kRow) * HID + n0 + (f0 + 16 * e) * 4);
        CP_COMMIT();
    }

    int bufIdx = 0;
    for (int ch = 0; ch < nch; ch++) {
        unsigned masks[RPW];
        #pragma unroll
        for (int r = 0; r < RPW; r++)
            masks[r] = Am[(size_t)(mA + r) * ws + ch];   // issue early (hide LDG)

        if (ch + 1 < nch) asm volatile("cp.async.wait_group 1;" ::: "memory");
        else              asm volatile("cp.async.wait_group 0;" ::: "memory");
        __syncthreads();   // buf[bufIdx] staged AND reads of the buf to be
                           // overwritten (used at ch-1) are complete

        // stage chunk ch+2 into the buffer freed at ch-1
        if (ch + 2 < nch) {
            int nb = bufIdx + 2; if (nb >= 3) nb -= 3;
            int k0 = (ch + 2) * 32;
            uint32_t dn = sb[nb];
            #pragma unroll
            for (int e = 0; e < 2; e++)
                cp16(dn + (uint32_t)(kRow * BS_P + (f0 + 16 * e) * 4) * 4,
                     B + (size_t)(k0 + kRow) * HID + n0 + (f0 + 16 * e) * 4);
            CP_COMMIT();
        }

        const float* Bsb = pool + bufIdx * CHUNK_FL;
        #pragma unroll
        for (int r = 0; r < RPW; r++)
            accum_mask(masks[r], Bsb, c0, acc[r]);

        if (++bufIdx == 3) bufIdx = 0;
    }

    // ---- fused LIF epilogue + spike-bit packing ----
    #pragma unroll
    for (int r = 0; r < RPW; r++) {
        size_t base = (size_t)(mA + r) * HID + n0 + c0;
        float4 vv = *(const float4*)&v[base];
        float t0 = vv.x * DECAY + acc[r][0];
        float t1 = vv.y * DECAY + acc[r][1];
        float t2 = vv.z * DECAY + acc[r][2];
        float t3 = vv.w * DECAY + acc[r][3];
        bool p0 = t0 >= THRESH, p1 = t1 >= THRESH, p2 = t2 >= THRESH, p3 = t3 >= THRESH;
        float4 vn;
        vn.x = p0 ? 0.0f : t0; vn.y = p1 ? 0.0f : t1;
        vn.z = p2 ? 0.0f : t2; vn.w = p3 ? 0.0f : t3;
        *(float4*)&v[base] = vn;
        unsigned nb = (unsigned)p0 | ((unsigned)p1 << 1) | ((unsigned)p2 << 2) | ((unsigned)p3 << 3);
        nib[(wid * RPW + r) * 32 + lane] = (unsigned char)nb;
    }
    __syncwarp();
    if (lane < RPW * 4) {                           // RPW rows x 4 words of 32 bits
        int r = lane >> 2, widx = lane & 3;
        unsigned w = 0;
        #pragma unroll
        for (int q = 0; q < 8; q++)
            w |= (unsigned)nib[(wid * RPW + r) * 32 + widx * 8 + q] << (4 * q);
        mOut[(size_t)(mA + r) * 64 + (n0 >> 5) + widx] = w;
    }
}

// ---------------- fused step ----------------
// blocks [0,256)   = L2(t):   16m x 128n, RPW=1, 64 chunks
// blocks [256,384) = L1(t+1): 32m x 128n, RPW=2, 32 chunks  (equal duration to L2 blocks)
// blocks [384,448) = OUT(t-1)
__global__ __launch_bounds__(512, 3) void fused_step_kernel(
    const unsigned* __restrict__ mXt,
    const float* __restrict__ W_ih,
    const float* __restrict__ W_hh,
    const float* __restrict__ W_ho,
    const unsigned* __restrict__ m1r, unsigned* __restrict__ m1w,
    const unsigned* __restrict__ m2r, unsigned* __restrict__ m2w,
    int doL1, int doL2, int doOUT)
{
    extern __shared__ char dyn[];
    float* pool = (float*)dyn;
    unsigned char* nib = (unsigned char*)(dyn + POOL_FL * 4);
    int blk = blockIdx.x;
    int tid = threadIdx.x;

    if (blk < 256) {                       // ---- L2(t): m1 @ W_hh -> v2, m2
        if (!doL2) return;
        gemm_sparse<1>(m1r, 64, W_hh, g_v2, m2w, HID, blk & 15, blk >> 4, pool, nib);
    } else if (blk < 384) {                // ---- L1(t+1): mX @ W_ih -> v1, m1
        if (!doL1) return;
        int b2 = blk - 256;
        gemm_sparse<2>(mXt, 32, W_ih, g_v1, m1w, IN_DIM, b2 & 15, b2 >> 4, pool, nib);
    } else {                               // ---- OUT(t-1): mask-driven, order == validated kernel
        if (!doOUT) return;
        int group = tid >> 7;              // 0..3
        int lt    = tid & 127;
        int b     = (blk - 384) * 4 + group;

        float accv[OUT_DIM];
        #pragma unroll
        for (int o = 0; o < OUT_DIM; o++) accv[o] = 0.0f;

        const unsigned* mrow = m2r + (size_t)b * 64;
        #pragma unroll 4
        for (int j = 0; j < HID / 128; j++) {
            int i = lt + j * 128;
            unsigned w = mrow[i >> 5];
            if ((w >> (i & 31)) & 1u) {
                #pragma unroll
                for (int o = 0; o < OUT_DIM; o++)
                    accv[o] += W_ho[(size_t)i * OUT_DIM + o];
            }
        }

        float* red = pool;                 // [4][OUT_DIM][128] = 5120 floats
        #pragma unroll
        for (int o = 0; o < OUT_DIM; o++) red[(group * OUT_DIM + o) * 128 + lt] = accv[o];
        __syncthreads();

        for (int stride = 64; stride > 0; stride >>= 1) {
            if (lt < stride) {
                #pragma unroll
                for (int o = 0; o < OUT_DIM; o++)
                    red[(group * OUT_DIM + o) * 128 + lt] +=
                        red[(group * OUT_DIM + o) * 128 + lt + stride];
            }
            __syncthreads();
        }

        if (lt < OUT_DIM) {
            float cur = red[(group * OUT_DIM + lt) * 128];
            int idx = b * OUT_DIM + lt;
            float vv = g_vout[idx] * DECAY + cur;
            bool sp = (vv >= THRESH);
            g_vout[idx] = sp ? 0.0f : vv;
            if (sp) g_acc[idx] += 1.0f;
        }
    }
}

__global__ void finalize_kernel(float* __restrict__ out)
{
    int i = blockIdx.x * 256 + threadIdx.x;
    if (i < BATCH * OUT_DIM) out[i] = g_acc[i] * (1.0f / T_STEPS);
}

// ---------------- launch ----------------
extern "C" void kernel_launch(void* const* d_in, const int* in_sizes, int n_in,
                              void* d_out, int out_size)
{
    const float* in_bins = (const float*)d_in[0];   // [256,1024,100]
    const float* W_ih    = (const float*)d_in[1];   // [1024,2048]
    const float* W_hh    = (const float*)d_in[2];   // [1,2048,2048]
    const float* W_ho    = (const float*)d_in[3];   // [2048,10]
    float* out = (float*)d_out;

    unsigned *mX, *m1, *m2;
    cudaGetSymbolAddress((void**)&mX, g_mX);
    cudaGetSymbolAddress((void**)&m1, g_m1);
    cudaGetSymbolAddress((void**)&m2, g_m2);

    cudaFuncSetAttribute(fused_step_kernel,
                         cudaFuncAttributeMaxDynamicSharedMemorySize, SMEM_DYN);

    // 1) build input bitmasks
    {
        dim3 grid((T_STEPS + 31) / 32, (BATCH * IN_DIM) / 32);
        maskify_kernel<<<grid, dim3(32, 8)>>>(in_bins);
    }
    // 2) zero persistent state
    zero_state_kernel<<<(BATCH * HID + 255) / 256, 256>>>();

    // 3) software-pipelined time loop: call i runs L1(t=i), L2(t=i-1), OUT(t=i-2)
    for (int i = 0; i <= T_STEPS + 1; i++) {
        int ti = (i < T_STEPS) ? i : (T_STEPS - 1);
        const unsigned* mXt = mX + (size_t)ti * (BATCH * 32);
        unsigned* m1w = m1 + (size_t)(i & 1) * (BATCH * 64);
        const unsigned* m1r = m1 + (size_t)((i - 1) & 1) * (BATCH * 64);
        unsigned* m2w = m2 + (size_t)((i - 1) & 1) * (BATCH * 64);
        const unsigned* m2r = m2 + (size_t)((i - 2) & 1) * (BATCH * 64);
        int doL1  = (i < T_STEPS);
        int doL2  = (i >= 1) && (i <= T_STEPS);
        int doOUT = (i >= 2);
        fused_step_kernel<<<448, 512, SMEM_DYN>>>(mXt, W_ih, W_hh, W_ho,
                                                  m1r, m1w, m2r, m2w,
                                                  doL1, doL2, doOUT);
    }

    // 4) finalize
    finalize_kernel<<<(BATCH * OUT_DIM + 255) / 256, 256>>>(out);
}